// round 15
// baseline (speedup 1.0000x reference)
#include <cuda_runtime.h>
#include <cstdint>

#define NB 16
#define NP 8192
#define NC 32
#define NG 512
#define NM 32
#define CAP2 224

// ---- scratch (static __device__, no allocations) ----
__device__ float g_xt[NB * 3 * NP];   // xyz transposed: [b][coord][point]
__device__ int   g_fps[NB * NG];      // FPS indices
__device__ float g_cent[NB * NG * 3]; // center coords (fps order)
__device__ float g_cnorm[NB * NG];    // center squared norms
__device__ int   g_order[NB * NG];    // morton order
__device__ float4 g_tmp[(size_t)NB * NG * 512]; // nbh rows in FPS order (64MB)

typedef unsigned long long ull;

// packed f32x2 helpers (per-lane IEEE rn -> bit-exact)
__device__ __forceinline__ ull pk2(float lo, float hi) {
    ull r;
    asm("mov.b64 %0, {%1, %2};" : "=l"(r) : "r"(__float_as_uint(lo)), "r"(__float_as_uint(hi)));
    return r;
}
__device__ __forceinline__ float2 upk2(ull v) {
    unsigned lo, hi;
    asm("mov.b64 {%0, %1}, %2;" : "=r"(lo), "=r"(hi) : "l"(v));
    return make_float2(__uint_as_float(lo), __uint_as_float(hi));
}
__device__ __forceinline__ ull padd(ull a, ull b) {
    ull r; asm("add.rn.f32x2 %0, %1, %2;" : "=l"(r) : "l"(a), "l"(b)); return r;
}
__device__ __forceinline__ ull pmul(ull a, ull b) {
    ull r; asm("mul.rn.f32x2 %0, %1, %2;" : "=l"(r) : "l"(a), "l"(b)); return r;
}

// monotonic float->uint key; -0.0 treated as +0.0
__device__ __forceinline__ unsigned fkey(float f) {
    unsigned u = __float_as_uint(f);
    if (u == 0x80000000u) u = 0u;
    return u ^ ((unsigned)((int)u >> 31) | 0x80000000u);
}

// PN tree (proven): rn(rn(x*x + z*z) + y*y)
__device__ __forceinline__ float norm3(float x, float y, float z) {
    return __fadd_rn(__fadd_rn(__fmul_rn(x, x), __fmul_rn(z, z)), __fmul_rn(y, y));
}

// ---------------------------------------------------------------------------
// K0: transpose xyz to SoA
// ---------------------------------------------------------------------------
__global__ void k_pre(const float* __restrict__ xyz) {
    int i = blockIdx.x * blockDim.x + threadIdx.x;
    if (i >= NB * NP) return;
    int b = i / NP, p = i - b * NP;
    g_xt[(b * 3 + 0) * NP + p] = xyz[3 * i + 0];
    g_xt[(b * 3 + 1) * NP + p] = xyz[3 * i + 1];
    g_xt[(b * 3 + 2) * NP + p] = xyz[3 * i + 2];
}

// ---------------------------------------------------------------------------
// K1: FPS. 1024 thr/block. ONE barrier/iter (parity double-buffered partials,
// every warp redundantly reduces, winner coords broadcast from smem mirror).
// Per-element argmax tracking replaced by deferred index search on match.
// Dynamic smem: 3 * 4096 ull = 96KB.
// ---------------------------------------------------------------------------
__global__ void __launch_bounds__(1024, 1) k_fps() {
    extern __shared__ ull dsm[];
    ull* sx = dsm;
    ull* sy = dsm + 4096;
    ull* sz = dsm + 8192;

    int b = blockIdx.x, t = threadIdx.x;
    const float* X = &g_xt[(b * 3 + 0) * NP];
    const float* Y = &g_xt[(b * 3 + 1) * NP];
    const float* Z = &g_xt[(b * 3 + 2) * NP];
    const ull* X2 = (const ull*)X;
    const ull* Y2 = (const ull*)Y;
    const ull* Z2 = (const ull*)Z;

    ull pxp[4], pyp[4], pzp[4];
    float mind[8];
#pragma unroll
    for (int r = 0; r < 4; r++) {
        pxp[r] = X2[t * 4 + r];
        pyp[r] = Y2[t * 4 + r];
        pzp[r] = Z2[t * 4 + r];
        sx[t * 4 + r] = pxp[r];
        sy[t * 4 + r] = pyp[r];
        sz[t * 4 + r] = pzp[r];
    }
#pragma unroll
    for (int r = 0; r < 8; r++) mind[r] = 1e10f;

    __shared__ unsigned s_pk[2][32], s_pi[2][32];
    if (t == 0) g_fps[b * NG] = 0;
    __syncthreads();

    int lane = t & 31, w = t >> 5;
    unsigned base = (unsigned)t * 8u;
    // initial "last" = point 0 (broadcast from mirror)
    float2 f0x = upk2(sx[0]), f0y = upk2(sy[0]), f0z = upk2(sz[0]);
    float lx = f0x.x, ly = f0y.x, lz = f0z.x;

    for (int k = 1; k < NG; k++) {
        ull nlx = pk2(-lx, -lx), nly = pk2(-ly, -ly), nlz = pk2(-lz, -lz);
        float2 dval[4];
#pragma unroll
        for (int r = 0; r < 4; r++) {
            ull dx = padd(pxp[r], nlx);
            ull dy = padd(pyp[r], nly);
            ull dz = padd(pzp[r], nlz);
            ull dd = padd(padd(pmul(dx, dx), pmul(dy, dy)), pmul(dz, dz));
            dval[r] = upk2(dd);
            mind[2 * r]     = fminf(mind[2 * r],     dval[r].x);
            mind[2 * r + 1] = fminf(mind[2 * r + 1], dval[r].y);
        }
        // thread max (value only; index deferred)
        float m01 = fmaxf(mind[0], mind[1]);
        float m23 = fmaxf(mind[2], mind[3]);
        float m45 = fmaxf(mind[4], mind[5]);
        float m67 = fmaxf(mind[6], mind[7]);
        float bv  = fmaxf(fmaxf(m01, m23), fmaxf(m45, m67));

        unsigned key  = __float_as_uint(bv);    // >=0 -> monotonic bits
        unsigned wmax = __reduce_max_sync(0xFFFFFFFFu, key);
        unsigned cand = 0xFFFFFFFFu;
        if (key == wmax) {  // rare: find FIRST local index equal to bv
            unsigned fr = 8;
#pragma unroll
            for (int r = 7; r >= 0; r--)
                if (mind[r] == bv) fr = (unsigned)r;
            cand = base + fr;
        }
        unsigned wi = __reduce_min_sync(0xFFFFFFFFu, cand);
        int par = k & 1;
        if (lane == 0) { s_pk[par][w] = wmax; s_pi[par][w] = wi; }
        __syncthreads();
        // every warp reduces the 32 partials (redundant but barrier-free)
        unsigned kk = s_pk[par][lane], ii = s_pi[par][lane];
        unsigned gmax = __reduce_max_sync(0xFFFFFFFFu, kk);
        unsigned c2   = (kk == gmax) ? ii : 0xFFFFFFFFu;
        unsigned gi   = __reduce_min_sync(0xFFFFFFFFu, c2);
        if (t == 0) g_fps[b * NG + k] = (int)gi;
        // broadcast winner coords from mirror
        int pair = (int)(gi >> 1);
        float2 fx = upk2(sx[pair]);
        float2 fy = upk2(sy[pair]);
        float2 fz = upk2(sz[pair]);
        bool hi = (gi & 1u);
        lx = hi ? fx.y : fx.x;
        ly = hi ? fy.y : fy.x;
        lz = hi ? fz.y : fz.x;
    }

    __syncthreads();
    // tail: centers + cnorms in FPS order
    if (t < NG) {
        int fi = g_fps[b * NG + t];
        float cx = X[fi], cy = Y[fi], cz = Z[fi];
        g_cent[(b * NG + t) * 3 + 0] = cx;
        g_cent[(b * NG + t) * 3 + 1] = cy;
        g_cent[(b * NG + t) * 3 + 2] = cz;
        g_cnorm[b * NG + t] = norm3(cx, cy, cz);
    }
}

// ---------------------------------------------------------------------------
// K2: blocks [0,16): morton chain. Blocks [16, 16+8192): KNN via radix-select.
// ---------------------------------------------------------------------------
__global__ void __launch_bounds__(256, 4) k_mk(const float* __restrict__ x) {
    __shared__ unsigned s_key[NP];        // 32KB keys (morton aliases this)
    __shared__ unsigned s_hist[2048];     // 8KB histogram
    __shared__ ull s_cand[32 + CAP2];     // 2KB candidates
    __shared__ unsigned s_wsum[8];
    __shared__ unsigned s_c1, s_c2, s_bstar, s_rb;
    __shared__ float s_xq[NC];
    __shared__ int s_knn[NM];
    __shared__ unsigned s_pk[8], s_pi[8], s_w;

    int t = threadIdx.x;
    int lane = t & 31, w = t >> 5;

    if (blockIdx.x < NB) {
        // ---------------- morton ----------------
        int b = blockIdx.x;
        float* s_cx = (float*)s_key;
        float* s_cy = s_cx + NG;
        float* s_cz = s_cx + 2 * NG;
        float* s_cn = s_cx + 3 * NG;
        for (int j = t; j < NG; j += 256) {
            s_cx[j] = g_cent[(b * NG + j) * 3 + 0];
            s_cy[j] = g_cent[(b * NG + j) * 3 + 1];
            s_cz[j] = g_cent[(b * NG + j) * 3 + 2];
            s_cn[j] = g_cnorm[b * NG + j];
        }
        if (t == 0) { s_w = 0; g_order[b * NG] = 0; }
        __syncthreads();

        int j1 = t, j2 = t + 256;
        float c1x = s_cx[j1], c1y = s_cy[j1], c1z = s_cz[j1], n1 = s_cn[j1];
        float c2x = s_cx[j2], c2y = s_cy[j2], c2z = s_cz[j2], n2 = s_cn[j2];
        bool a1 = (j1 != 0), a2 = true;

        for (int k = 1; k < NG; k++) {
            int wi0 = (int)s_w;
            float qx = s_cx[wi0], qy = s_cy[wi0], qz = s_cz[wi0], qn = s_cn[wi0];
            float dot1 = fmaf(qz, c1z, fmaf(qy, c1y, __fmul_rn(qx, c1x)));
            float d21 = __fsub_rn(__fadd_rn(qn, n1), __fmul_rn(2.0f, dot1));
            float dv1 = __fsqrt_rn(fmaxf(d21, 0.0f));
            unsigned k1 = a1 ? __float_as_uint(dv1) : 0xFFFFFFFFu;
            float dot2 = fmaf(qz, c2z, fmaf(qy, c2y, __fmul_rn(qx, c2x)));
            float d22 = __fsub_rn(__fadd_rn(qn, n2), __fmul_rn(2.0f, dot2));
            float dv2 = __fsqrt_rn(fmaxf(d22, 0.0f));
            unsigned k2 = a2 ? __float_as_uint(dv2) : 0xFFFFFFFFu;
            unsigned kk = (k1 <= k2) ? k1 : k2;
            unsigned ii = (k1 <= k2) ? (unsigned)j1 : (unsigned)j2;

            unsigned kmin = __reduce_min_sync(0xFFFFFFFFu, kk);
            unsigned cand = (kk == kmin) ? ii : 0xFFFFFFFFu;
            unsigned imin = __reduce_min_sync(0xFFFFFFFFu, cand);
            if (lane == 0) { s_pk[w] = kmin; s_pi[w] = imin; }
            __syncthreads();
            if (w == 0 && lane < 8) {
                unsigned kb = s_pk[lane], ib = s_pi[lane];
                unsigned gmin = __reduce_min_sync(0xFFu, kb);
                unsigned cb   = (kb == gmin) ? ib : 0xFFFFFFFFu;
                unsigned gi   = __reduce_min_sync(0xFFu, cb);
                if (lane == 0) { s_w = gi; g_order[b * NG + k] = (int)gi; }
            }
            __syncthreads();
            int wn = (int)s_w;
            if (j1 == wn) a1 = false;
            if (j2 == wn) a2 = false;
        }
        return;
    }

    // ---------------- knn (radix-select top-32) ----------------
    int bg = blockIdx.x - NB;
    int b = bg >> 9;
    float cx = g_cent[bg * 3 + 0];
    float cy = g_cent[bg * 3 + 1];
    float cz = g_cent[bg * 3 + 2];
    float nc = g_cnorm[bg];
    int qi = g_fps[bg];
    const float* xb = x + (size_t)b * NP * NC;
    if (t < NC) s_xq[t] = xb[(size_t)qi * NC + t];

    const ull* X2 = (const ull*)&g_xt[(b * 3 + 0) * NP];
    const ull* Y2 = (const ull*)&g_xt[(b * 3 + 1) * NP];
    const ull* Z2 = (const ull*)&g_xt[(b * 3 + 2) * NP];

    // zero hist + counters
    for (int j = t; j < 2048; j += 256) s_hist[j] = 0;
    if (t == 0) { s_c1 = 0; s_c2 = 0; }
    __syncthreads();

    // distance + key + histogram (64-bit loads; pn recomputed, bit-identical)
#pragma unroll
    for (int r = 0; r < 16; r++) {
        int j = t + r * 256;            // pair index
        float2 xx = upk2(X2[j]);
        float2 yy = upk2(Y2[j]);
        float2 zz = upk2(Z2[j]);
        int i0 = 2 * j;
        {
            float pn = norm3(xx.x, yy.x, zz.x);
            float dot = fmaf(cz, zz.x, fmaf(cy, yy.x, __fmul_rn(cx, xx.x)));
            float d2 = __fsub_rn(__fadd_rn(nc, pn), __fmul_rn(2.0f, dot));
            unsigned kk = fkey(d2);
            s_key[i0] = kk;
            atomicAdd(&s_hist[kk >> 21], 1u);
        }
        {
            float pn = norm3(xx.y, yy.y, zz.y);
            float dot = fmaf(cz, zz.y, fmaf(cy, yy.y, __fmul_rn(cx, xx.y)));
            float d2 = __fsub_rn(__fadd_rn(nc, pn), __fmul_rn(2.0f, dot));
            unsigned kk = fkey(d2);
            s_key[i0 + 1] = kk;
            atomicAdd(&s_hist[kk >> 21], 1u);
        }
    }
    __syncthreads();

    // block scan over 2048 bins -> find bin containing rank 32
    {
        int hb = t * 8;
        unsigned part = 0;
#pragma unroll
        for (int j = 0; j < 8; j++) part += s_hist[hb + j];
        unsigned inc = part;
#pragma unroll
        for (int d = 1; d < 32; d <<= 1) {
            unsigned v = __shfl_up_sync(0xFFFFFFFFu, inc, d);
            if (lane >= d) inc += v;
        }
        if (lane == 31) s_wsum[w] = inc;
        __syncthreads();
        if (w == 0 && lane < 8) {
            unsigned v = s_wsum[lane];
            unsigned inc2 = v;
#pragma unroll
            for (int d = 1; d < 8; d <<= 1) {
                unsigned u2 = __shfl_up_sync(0xFFu, inc2, d);
                if (lane >= d) inc2 += u2;
            }
            s_wsum[lane] = inc2 - v; // exclusive warp offset
        }
        __syncthreads();
        unsigned run = s_wsum[w] + inc - part; // exclusive prefix before bin hb
#pragma unroll
        for (int j = 0; j < 8; j++) {
            unsigned h = s_hist[hb + j];
            if (run < 32u && run + h >= 32u) { s_bstar = (unsigned)(hb + j); s_rb = run; }
            run += h;
        }
    }
    __syncthreads();

    unsigned bstar = s_bstar;
    // collect: bins < bstar -> definite; bin == bstar -> boundary candidates
#pragma unroll
    for (int r = 0; r < 32; r++) {
        int i = t + r * 256;
        unsigned kk = s_key[i];
        unsigned bin = kk >> 21;
        if (bin < bstar) {
            unsigned p = atomicAdd(&s_c1, 1u);
            s_cand[p] = ((ull)kk << 32) | (unsigned)i;
        } else if (bin == bstar) {
            unsigned p = atomicAdd(&s_c2, 1u);
            if (p < CAP2) s_cand[32 + p] = ((ull)kk << 32) | (unsigned)i;
        }
    }
    __syncthreads();

    if (s_c2 <= CAP2) {
        // rank-by-count over n1 + n2 candidates (unique ulls -> exact order)
        int n1 = (int)s_c1, n2 = (int)s_c2;
        for (int e = t; e < n1 + n2; e += 256) {
            int pos = (e < n1) ? e : 32 + (e - n1);
            ull v = s_cand[pos];
            unsigned rk = 0;
            for (int q = 0; q < n1; q++) rk += (s_cand[q] < v);
            for (int q = 0; q < n2; q++) rk += (s_cand[32 + q] < v);
            if (rk < 32u) s_knn[rk] = (int)(unsigned)(v & 0xFFFFFFFFull);
        }
        __syncthreads();
    } else {
        // fallback (degenerate tie storm): legacy 32-round selection on keys
        unsigned bk = 0xFFFFFFFFu, bi = 0xFFFFFFFFu;
#pragma unroll
        for (int r = 0; r < 32; r++) {
            int i = t + r * 256;
            unsigned kk = s_key[i];
            if (kk < bk) { bk = kk; bi = (unsigned)i; }
        }
        __syncthreads();
        for (int k = 0; k < NM; k++) {
            unsigned kmin = __reduce_min_sync(0xFFFFFFFFu, bk);
            unsigned cand = (bk == kmin) ? bi : 0xFFFFFFFFu;
            unsigned imin = __reduce_min_sync(0xFFFFFFFFu, cand);
            if (lane == 0) { s_pk[w] = kmin; s_pi[w] = imin; }
            __syncthreads();
            if (w == 0 && lane < 8) {
                unsigned kb = s_pk[lane], ib = s_pi[lane];
                unsigned gmin = __reduce_min_sync(0xFFu, kb);
                unsigned cb   = (kb == gmin) ? ib : 0xFFFFFFFFu;
                unsigned gi   = __reduce_min_sync(0xFFu, cb);
                if (lane == 0) { s_w = gi; s_knn[k] = (int)gi; }
            }
            __syncthreads();
            unsigned wi = s_w;
            if ((wi & 255u) == (unsigned)t) {
                s_key[wi] = 0xFFFFFFFFu;
                bk = 0xFFFFFFFFu; bi = 0xFFFFFFFFu;
#pragma unroll
                for (int r = 0; r < 32; r++) {
                    int i = t + r * 256;
                    unsigned kk = s_key[i];
                    if (kk < bk) { bk = kk; bi = (unsigned)i; }
                }
            }
        }
        __syncthreads();
    }

    // write nbh row (FPS order) to g_tmp
    float* trow = (float*)&g_tmp[(size_t)bg * 512];
    for (int v = t; v < NM * 2 * NC; v += 256) {
        int m = v >> 6, cc = v & 63;
        float val;
        if (cc < NC) val = __fsub_rn(xb[(size_t)s_knn[m] * NC + cc], s_xq[cc]);
        else         val = s_xq[cc - NC];
        trow[v] = val;
    }
}

// ---------------------------------------------------------------------------
// K3: scatter rows by morton order + write centers
// ---------------------------------------------------------------------------
__global__ void __launch_bounds__(256, 8) k_scat(float* __restrict__ out) {
    int bg = blockIdx.x;
    int b = bg >> 9;
    int t = threadIdx.x;
    int g = g_order[bg];
    const float4* src = &g_tmp[((size_t)b * NG + g) * 512];
    float4* dst = (float4*)out + (size_t)bg * 512;
    dst[t] = src[t];
    dst[t + 256] = src[t + 256];
    if (t < 3)
        out[(size_t)NB * NG * NM * 2 * NC + (size_t)bg * 3 + t] =
            g_cent[(b * NG + g) * 3 + t];
}

// ---------------------------------------------------------------------------
extern "C" void kernel_launch(void* const* d_in, const int* in_sizes, int n_in,
                              void* d_out, int out_size) {
    const float* x   = (const float*)d_in[0];
    const float* xyz = (const float*)d_in[1];
    if (n_in >= 2 && in_sizes[0] == NB * NP * 3) { // defensive: metadata order swap
        const float* tmp = x; x = xyz; xyz = tmp;
    }
    float* out = (float*)d_out;

    static bool inited = false;
    if (!inited) {
        cudaFuncSetAttribute(k_fps, cudaFuncAttributeMaxDynamicSharedMemorySize,
                             3 * 4096 * (int)sizeof(ull));
        inited = true;
    }

    k_pre<<<(NB * NP + 255) / 256, 256>>>(xyz);
    k_fps<<<NB, 1024, 3 * 4096 * sizeof(ull)>>>();
    k_mk<<<NB + NB * NG, 256>>>(x);
    k_scat<<<NB * NG, 256>>>(out);
}